// round 2
// baseline (speedup 1.0000x reference)
#include <cuda_runtime.h>
#include <cstdint>

#define V 12288
#define CIN 16
#define COUT 32
#define KORD 5
#define CU 256           // u-chunk per stage buffer
#define NC (V / CU)      // 48 chunks
#define VT 16            // v rows per CTA
#define CV (CIN * V)

// Scratch for T1..T4 (T0 == x read directly). 4 * 16 * 12288 * 4B = 3.1 MB.
__device__ float g_T[4 * CV];

__device__ __forceinline__ void cp_async16(uint32_t dst, const float* src) {
    asm volatile("cp.async.cg.shared.global [%0], [%1], 16;\n" :: "r"(dst), "l"(src));
}
__device__ __forceinline__ void cp_commit() {
    asm volatile("cp.async.commit_group;\n");
}
template <int N>
__device__ __forceinline__ void cp_wait() {
    asm volatile("cp.async.wait_group %0;\n" :: "n"(N));
}

// acc (f32x2) += (ax,ay) * (bx,by)
__device__ __forceinline__ void ffma2(unsigned long long& acc,
                                      float ax, float ay, float bx, float by) {
    unsigned long long a, b;
    asm("mov.b64 %0, {%1, %2};" : "=l"(a) : "f"(ax), "f"(ay));
    asm("mov.b64 %0, {%1, %2};" : "=l"(b) : "f"(bx), "f"(by));
    asm("fma.rn.f32x2 %0, %1, %2, %0;" : "+l"(acc) : "l"(a), "l"(b));
}

// O[i][v] = alpha * sum_u A[i][u] * L[v][u] + beta * P[i][v]
// A,P,O: [CIN][V] row-major.  L: [V][V] row-major.
// CTA: 256 threads = 8 warps. Warp w: channel-half h = w&1 (channels 8h..8h+7),
// v-group g = w>>1 (4 v rows). Lanes split u (4 consecutive u per lane per step).
__global__ __launch_bounds__(256, 2)
void cheb_pass(const float* __restrict__ A,
               const float* __restrict__ L,
               const float* __restrict__ P,
               float* __restrict__ O,
               float alpha, float beta)
{
    __shared__ float As[2][CIN][CU];   // 2 x 16KB, plain row-major (conflict-free)

    const int tid  = threadIdx.x;
    const int w    = tid >> 5;
    const int lane = tid & 31;
    const int chb  = (w & 1) * 8;                 // channel base for this warp
    const int v0   = blockIdx.x * VT + (w >> 1) * 4;

    const float* Lr0 = L + (size_t)(v0 + 0) * V;
    const float* Lr1 = L + (size_t)(v0 + 1) * V;
    const float* Lr2 = L + (size_t)(v0 + 2) * V;
    const float* Lr3 = L + (size_t)(v0 + 3) * V;

    unsigned long long acc[8][4];
#pragma unroll
    for (int c = 0; c < 8; c++)
#pragma unroll
        for (int vv = 0; vv < 4; vv++) acc[c][vv] = 0ULL;

    // ---- stage chunk 0 ----
#pragma unroll
    for (int k = 0; k < 4; k++) {
        int g  = k * 256 + tid;          // 0..1023 16B-units
        int ch = g >> 6;
        int un = (g & 63) << 2;          // float index within row
        cp_async16((uint32_t)__cvta_generic_to_shared(&As[0][ch][un]),
                   A + (size_t)ch * V + un);
    }
    cp_commit();

    for (int cc = 0; cc < NC; cc++) {
        const int b  = cc & 1;
        const int u0 = cc * CU;

        if (cc + 1 < NC) {
            const int u0n = u0 + CU;
#pragma unroll
            for (int k = 0; k < 4; k++) {
                int g  = k * 256 + tid;
                int ch = g >> 6;
                int un = (g & 63) << 2;
                cp_async16((uint32_t)__cvta_generic_to_shared(&As[b ^ 1][ch][un]),
                           A + (size_t)ch * V + u0n + un);
            }
            cp_commit();
            cp_wait<1>();     // chunk cc complete; cc+1 may remain in flight
        } else {
            cp_wait<0>();
        }
        __syncthreads();

#pragma unroll
        for (int t = 0; t < 2; t++) {
            const int uo = t * 128 + 4 * lane;
            const float4 l0 = __ldcs((const float4*)(Lr0 + u0 + uo));
            const float4 l1 = __ldcs((const float4*)(Lr1 + u0 + uo));
            const float4 l2 = __ldcs((const float4*)(Lr2 + u0 + uo));
            const float4 l3 = __ldcs((const float4*)(Lr3 + u0 + uo));
#pragma unroll
            for (int c = 0; c < 8; c++) {
                const float4 a = *(const float4*)(&As[b][chb + c][uo]);
                ffma2(acc[c][0], a.x, a.y, l0.x, l0.y);
                ffma2(acc[c][0], a.z, a.w, l0.z, l0.w);
                ffma2(acc[c][1], a.x, a.y, l1.x, l1.y);
                ffma2(acc[c][1], a.z, a.w, l1.z, l1.w);
                ffma2(acc[c][2], a.x, a.y, l2.x, l2.y);
                ffma2(acc[c][2], a.z, a.w, l2.z, l2.w);
                ffma2(acc[c][3], a.x, a.y, l3.x, l3.y);
                ffma2(acc[c][3], a.z, a.w, l3.z, l3.w);
            }
        }
        __syncthreads();
    }

    // ---- reduce across u-parity halves and lanes; fused recurrence epilogue ----
#pragma unroll
    for (int c = 0; c < 8; c++) {
#pragma unroll
        for (int vv = 0; vv < 4; vv++) {
            unsigned lo_u, hi_u;
            asm("mov.b64 {%0, %1}, %2;" : "=r"(lo_u), "=r"(hi_u) : "l"(acc[c][vv]));
            float s = __uint_as_float(lo_u) + __uint_as_float(hi_u);
#pragma unroll
            for (int off = 16; off; off >>= 1)
                s += __shfl_xor_sync(0xFFFFFFFFu, s, off);
            if (lane == (c * 4 + vv)) {
                const int i = chb + c;
                const int v = v0 + vv;
                float r = alpha * s;
                if (beta != 0.0f) r += beta * P[(size_t)i * V + v];
                O[(size_t)i * V + v] = r;
            }
        }
    }
}

// out[o][v] = bias[o] + sum_k sum_i T_k[i][v] * W[k][i][o]
__global__ __launch_bounds__(128)
void cheb_combine(const float* __restrict__ x,
                  const float* __restrict__ Wt,
                  const float* __restrict__ bias,
                  float* __restrict__ out)
{
    __shared__ float Ws[KORD * CIN * COUT];
    __shared__ float bs[COUT];
    const int tid = threadIdx.x;
    for (int idx = tid; idx < KORD * CIN * COUT; idx += blockDim.x) Ws[idx] = Wt[idx];
    if (tid < COUT) bs[tid] = bias[tid];
    __syncthreads();

    const int v = blockIdx.x * blockDim.x + tid;

    float acc[COUT];
#pragma unroll
    for (int o = 0; o < COUT; o++) acc[o] = bs[o];

#pragma unroll
    for (int k = 0; k < KORD; k++) {
        const float* T = (k == 0) ? x : (g_T + (size_t)(k - 1) * CV);
#pragma unroll
        for (int i = 0; i < CIN; i++) {
            float tv = T[(size_t)i * V + v];
            const float* wrow = &Ws[(k * CIN + i) * COUT];
#pragma unroll
            for (int o = 0; o < COUT; o++) acc[o] = fmaf(tv, wrow[o], acc[o]);
        }
    }
#pragma unroll
    for (int o = 0; o < COUT; o++) out[(size_t)o * V + v] = acc[o];
}

extern "C" void kernel_launch(void* const* d_in, const int* in_sizes, int n_in,
                              void* d_out, int out_size)
{
    const float* x  = (const float*)d_in[0];
    const float* L  = (const float*)d_in[1];
    const float* Wt = (const float*)d_in[2];
    const float* b  = (const float*)d_in[3];
    float* out = (float*)d_out;

    float* gT = nullptr;
    cudaGetSymbolAddress((void**)&gT, g_T);

    const dim3 grid(V / VT);   // 768 CTAs
    const dim3 blk(256);

    // T1 = x @ L^T
    cheb_pass<<<grid, blk>>>(x, L, x, gT + 0 * CV, 1.0f, 0.0f);
    // T2 = 2 T1 @ L^T - x
    cheb_pass<<<grid, blk>>>(gT + 0 * CV, L, x, gT + 1 * CV, 2.0f, -1.0f);
    // T3 = 2 T2 @ L^T - T1
    cheb_pass<<<grid, blk>>>(gT + 1 * CV, L, gT + 0 * CV, gT + 2 * CV, 2.0f, -1.0f);
    // T4 = 2 T3 @ L^T - T2
    cheb_pass<<<grid, blk>>>(gT + 2 * CV, L, gT + 1 * CV, gT + 3 * CV, 2.0f, -1.0f);
    // out = einsum + bias
    cheb_combine<<<V / 128, 128>>>(x, Wt, b, out);
}

// round 3
// speedup vs baseline: 1.1116x; 1.1116x over previous
#include <cuda_runtime.h>
#include <cstdint>

#define V 12288
#define CIN 16
#define NP 8              // channel pairs
#define COUT 32
#define KORD 5
#define CU 256            // u-chunk per stage buffer
#define NC (V / CU)       // 48 chunks
#define VT 32             // v rows per CTA
#define PV (NP * V)       // float2 elements per tensor

// Channel-pair-interleaved tensors: T[p][v] = (T[2p][v], T[2p+1][v])
__device__ float2 g_xp[PV];          // interleaved x
__device__ float2 g_Tp[4][PV];       // T1..T4

__device__ __forceinline__ void cp_async16(uint32_t dst, const void* src) {
    asm volatile("cp.async.cg.shared.global [%0], [%1], 16;\n" :: "r"(dst), "l"(src));
}
__device__ __forceinline__ void cp_commit() {
    asm volatile("cp.async.commit_group;\n");
}
template <int N>
__device__ __forceinline__ void cp_wait() {
    asm volatile("cp.async.wait_group %0;\n" :: "n"(N));
}

__device__ __forceinline__ unsigned long long pack2(float x) {
    unsigned long long r;
    unsigned xi = __float_as_uint(x);
    asm("mov.b64 %0, {%1, %2};" : "=l"(r) : "r"(xi), "r"(xi));
    return r;
}
__device__ __forceinline__ void fma2(unsigned long long& acc,
                                     unsigned long long a,
                                     unsigned long long b) {
    asm("fma.rn.f32x2 %0, %1, %2, %0;" : "+l"(acc) : "l"(a), "l"(b));
}

// Op[p][v] = alpha * sum_u Ap[p][u](pairwise) * L[v][u] + beta * Pp[p][v]
// Ap/Pp/Op: float2[NP][V] channel-pair-interleaved. L: [V][V] fp32 row-major.
// CTA: 8 warps. warp w: c-half h=w&1 (pairs 4h..4h+3), v-group w>>1 (8 v rows).
__global__ __launch_bounds__(256, 2)
void cheb_pass(const float2* __restrict__ Ap,
               const float* __restrict__ L,
               const float2* __restrict__ Pp,
               float2* __restrict__ Op,
               float alpha, float beta)
{
    __shared__ float2 As[2][NP][CU];   // 2 x 16KB

    const int tid  = threadIdx.x;
    const int w    = tid >> 5;
    const int lane = tid & 31;
    const int pb   = (w & 1) * 4;                    // pair base
    const int v0   = blockIdx.x * VT + (w >> 1) * 8; // 8 v rows

    const float* lb = L + (size_t)v0 * V;

    unsigned long long acc[4][8];
#pragma unroll
    for (int j = 0; j < 4; j++)
#pragma unroll
        for (int r = 0; r < 8; r++) acc[j][r] = 0ULL;

    // stage chunk 0: 8 pairs x 256 u x 8B = 16KB = 1024 x 16B
#pragma unroll
    for (int k = 0; k < 4; k++) {
        int idx = k * 256 + tid;
        int p   = idx >> 7;            // 128 16B-units per pair row
        int uo  = (idx & 127) * 2;
        cp_async16((uint32_t)__cvta_generic_to_shared(&As[0][p][uo]),
                   Ap + (size_t)p * V + uo);
    }
    cp_commit();

    for (int cc = 0; cc < NC; cc++) {
        const int b  = cc & 1;
        const int u0 = cc * CU;

        if (cc + 1 < NC) {
            const int u0n = u0 + CU;
#pragma unroll
            for (int k = 0; k < 4; k++) {
                int idx = k * 256 + tid;
                int p   = idx >> 7;
                int uo  = (idx & 127) * 2;
                cp_async16((uint32_t)__cvta_generic_to_shared(&As[b ^ 1][p][uo]),
                           Ap + (size_t)p * V + u0n + uo);
            }
            cp_commit();
            cp_wait<1>();
        } else {
            cp_wait<0>();
        }
        __syncthreads();

#pragma unroll
        for (int t = 0; t < 4; t++) {
            const int uo = 64 * t + 2 * lane;

            // L: 8 rows, float2 each (batched for MLP)
            float2 lv[8];
#pragma unroll
            for (int r = 0; r < 8; r++)
                lv[r] = *(const float2*)(lb + (size_t)r * V + u0 + uo);

            // A: 4 pairs x 2 u (16B each, conflict-free)
            ulonglong2 av[4];
#pragma unroll
            for (int j = 0; j < 4; j++)
                av[j] = *(const ulonglong2*)(&As[b][pb + j][uo]);

#pragma unroll
            for (int r = 0; r < 8; r++) {
                unsigned long long bx = pack2(lv[r].x);
                unsigned long long by = pack2(lv[r].y);
#pragma unroll
                for (int j = 0; j < 4; j++) {
                    fma2(acc[j][r], av[j].x, bx);
                    fma2(acc[j][r], av[j].y, by);
                }
            }
        }
        __syncthreads();
    }

    // reduce over lanes (u was lane-sliced); one (j,r) result per lane
#pragma unroll
    for (int j = 0; j < 4; j++) {
#pragma unroll
        for (int r = 0; r < 8; r++) {
            unsigned lo_u, hi_u;
            asm("mov.b64 {%0, %1}, %2;" : "=r"(lo_u), "=r"(hi_u) : "l"(acc[j][r]));
            float sx = __uint_as_float(lo_u);   // channel 2p
            float sy = __uint_as_float(hi_u);   // channel 2p+1
#pragma unroll
            for (int off = 16; off; off >>= 1) {
                sx += __shfl_xor_sync(0xFFFFFFFFu, sx, off);
                sy += __shfl_xor_sync(0xFFFFFFFFu, sy, off);
            }
            if (lane == (j * 8 + r)) {
                const int p = pb + j;
                const int v = v0 + r;
                float2 res;
                res.x = alpha * sx;
                res.y = alpha * sy;
                if (beta != 0.0f) {
                    float2 pv = Pp[(size_t)p * V + v];
                    res.x += beta * pv.x;
                    res.y += beta * pv.y;
                }
                Op[(size_t)p * V + v] = res;
            }
        }
    }
}

// interleave x into g_xp
__global__ void prep_x(const float* __restrict__ x)
{
    const int v = blockIdx.x * blockDim.x + threadIdx.x;
    const int p = blockIdx.y;
    g_xp[(size_t)p * V + v] =
        make_float2(x[(size_t)(2 * p) * V + v], x[(size_t)(2 * p + 1) * V + v]);
}

// out[o][v] = bias[o] + sum_k sum_p (Tk[p][v].x * W[k][2p][o] + .y * W[k][2p+1][o])
__global__ __launch_bounds__(128)
void cheb_combine(const float* __restrict__ Wt,
                  const float* __restrict__ bias,
                  float* __restrict__ out)
{
    __shared__ float Ws[KORD * CIN * COUT];
    __shared__ float bs[COUT];
    const int tid = threadIdx.x;
    for (int idx = tid; idx < KORD * CIN * COUT; idx += blockDim.x) Ws[idx] = Wt[idx];
    if (tid < COUT) bs[tid] = bias[tid];
    __syncthreads();

    const int v = blockIdx.x * blockDim.x + tid;

    float acc[COUT];
#pragma unroll
    for (int o = 0; o < COUT; o++) acc[o] = bs[o];

#pragma unroll
    for (int k = 0; k < KORD; k++) {
        const float2* T = (k == 0) ? g_xp : g_Tp[k - 1];
#pragma unroll
        for (int p = 0; p < NP; p++) {
            float2 tv = T[(size_t)p * V + v];
            const float* w0 = &Ws[(k * CIN + 2 * p) * COUT];
            const float* w1 = w0 + COUT;
#pragma unroll
            for (int o = 0; o < COUT; o++)
                acc[o] = fmaf(tv.x, w0[o], fmaf(tv.y, w1[o], acc[o]));
        }
    }
#pragma unroll
    for (int o = 0; o < COUT; o++) out[(size_t)o * V + v] = acc[o];
}

extern "C" void kernel_launch(void* const* d_in, const int* in_sizes, int n_in,
                              void* d_out, int out_size)
{
    const float* x  = (const float*)d_in[0];
    const float* L  = (const float*)d_in[1];
    const float* Wt = (const float*)d_in[2];
    const float* b  = (const float*)d_in[3];
    float* out = (float*)d_out;

    float2* xp = nullptr;
    float2* Tp = nullptr;
    cudaGetSymbolAddress((void**)&xp, g_xp);
    cudaGetSymbolAddress((void**)&Tp, g_Tp);

    prep_x<<<dim3(V / 256, NP), 256>>>(x);

    const dim3 grid(V / VT);   // 384 CTAs
    const dim3 blk(256);

    // T1 = x @ L^T
    cheb_pass<<<grid, blk>>>(xp, L, xp, Tp + 0 * PV, 1.0f, 0.0f);
    // T2 = 2 T1 @ L^T - x
    cheb_pass<<<grid, blk>>>(Tp + 0 * PV, L, xp, Tp + 1 * PV, 2.0f, -1.0f);
    // T3 = 2 T2 @ L^T - T1
    cheb_pass<<<grid, blk>>>(Tp + 1 * PV, L, Tp + 0 * PV, Tp + 2 * PV, 2.0f, -1.0f);
    // T4 = 2 T3 @ L^T - T2
    cheb_pass<<<grid, blk>>>(Tp + 2 * PV, L, Tp + 1 * PV, Tp + 3 * PV, 2.0f, -1.0f);
    // out = einsum + bias
    cheb_combine<<<V / 128, 128>>>(Wt, b, out);
}

// round 4
// speedup vs baseline: 1.6447x; 1.4797x over previous
#include <cuda_runtime.h>
#include <cstdint>

#define V 12288
#define CIN 16
#define NP 8              // channel pairs
#define COUT 32
#define KORD 5
#define CU 256            // u-chunk per stage buffer
#define NC (V / CU)       // 48 chunks
#define VT 32             // v rows per CTA
#define PV (NP * V)       // float2 elements per tensor

// Channel-pair-interleaved tensors: T[p][v] = (T[2p][v], T[2p+1][v])
__device__ float2 g_xp[PV];          // interleaved x
__device__ float2 g_Tp[4][PV];       // T1..T4

__device__ __forceinline__ void cp_async16(uint32_t dst, const void* src) {
    asm volatile("cp.async.cg.shared.global [%0], [%1], 16;\n" :: "r"(dst), "l"(src));
}
__device__ __forceinline__ void cp_commit() {
    asm volatile("cp.async.commit_group;\n");
}
template <int N>
__device__ __forceinline__ void cp_wait() {
    asm volatile("cp.async.wait_group %0;\n" :: "n"(N));
}

__device__ __forceinline__ unsigned long long pack2(float x) {
    unsigned long long r;
    unsigned xi = __float_as_uint(x);
    asm("mov.b64 %0, {%1, %2};" : "=l"(r) : "r"(xi), "r"(xi));
    return r;
}
__device__ __forceinline__ void fma2(unsigned long long& acc,
                                     unsigned long long a,
                                     unsigned long long b) {
    asm("fma.rn.f32x2 %0, %1, %2, %0;" : "+l"(acc) : "l"(a), "l"(b));
}

// Op[p][v] = alpha * sum_u Ap[p][u](pairwise over channels) * L[v][u] + beta * Pp[p][v]
// Warp w owns v rows v0..v0+3 (ALL 8 channel pairs) -> no L duplication.
// Lane u-slice: 2 consecutive u per lane per step (S = 64 u per warp-step).
__global__ __launch_bounds__(256, 2)
void cheb_pass(const float2* __restrict__ Ap,
               const float* __restrict__ L,
               const float2* __restrict__ Pp,
               float2* __restrict__ Op,
               float alpha, float beta)
{
    __shared__ float2 As[2][NP][CU];   // 2 x 16KB

    const int tid  = threadIdx.x;
    const int w    = tid >> 5;
    const int lane = tid & 31;
    const int v0   = blockIdx.x * VT + w * 4;  // 4 v rows per warp

    const float* lb = L + (size_t)v0 * V;

    unsigned long long acc[NP][4];
#pragma unroll
    for (int p = 0; p < NP; p++)
#pragma unroll
        for (int r = 0; r < 4; r++) acc[p][r] = 0ULL;

    // ---- stage chunk 0: 8 pairs x 256 u x 8B = 16KB = 1024 x 16B ----
#pragma unroll
    for (int k = 0; k < 4; k++) {
        int idx = k * 256 + tid;
        int p   = idx >> 7;            // 128 16B-units per pair row
        int uo  = (idx & 127) * 2;
        cp_async16((uint32_t)__cvta_generic_to_shared(&As[0][p][uo]),
                   Ap + (size_t)p * V + uo);
    }
    cp_commit();

    // ---- L register prefetch: step 0 ----
    float2 lv[4], lvn[4];
    {
        const int u = 2 * lane;
#pragma unroll
        for (int r = 0; r < 4; r++)
            lv[r] = __ldcs((const float2*)(lb + (size_t)r * V + u));
    }

    for (int cc = 0; cc < NC; cc++) {
        const int b = cc & 1;

        if (cc + 1 < NC) {
            const int u0n = (cc + 1) * CU;
#pragma unroll
            for (int k = 0; k < 4; k++) {
                int idx = k * 256 + tid;
                int p   = idx >> 7;
                int uo  = (idx & 127) * 2;
                cp_async16((uint32_t)__cvta_generic_to_shared(&As[b ^ 1][p][uo]),
                           Ap + (size_t)p * V + u0n + uo);
            }
            cp_commit();
            cp_wait<1>();
        } else {
            cp_wait<0>();
        }
        __syncthreads();

#pragma unroll
        for (int t = 0; t < 4; t++) {
            const int ul = 64 * t + 2 * lane;       // u within chunk
            // prefetch L for next step (wraps harmlessly at the very end)
            int un = cc * CU + ul + 64;
            if (un >= V) un = 2 * lane;
#pragma unroll
            for (int r = 0; r < 4; r++)
                lvn[r] = __ldcs((const float2*)(lb + (size_t)r * V + un));

            // A: 8 pairs x 2 u each (LDS.128, lanes hit consecutive 16B units)
            ulonglong2 av[NP];
#pragma unroll
            for (int p = 0; p < NP; p++)
                av[p] = *(const ulonglong2*)(&As[b][p][ul]);

#pragma unroll
            for (int r = 0; r < 4; r++) {
                unsigned long long bx = pack2(lv[r].x);
                unsigned long long by = pack2(lv[r].y);
#pragma unroll
                for (int p = 0; p < NP; p++) {
                    fma2(acc[p][r], av[p].x, bx);
                    fma2(acc[p][r], av[p].y, by);
                }
            }
#pragma unroll
            for (int r = 0; r < 4; r++) lv[r] = lvn[r];
        }
        __syncthreads();
    }

    // ---- lane reduce (u was lane-sliced); one (p,r) result per lane ----
#pragma unroll
    for (int p = 0; p < NP; p++) {
#pragma unroll
        for (int r = 0; r < 4; r++) {
            unsigned lo_u, hi_u;
            asm("mov.b64 {%0, %1}, %2;" : "=r"(lo_u), "=r"(hi_u) : "l"(acc[p][r]));
            float sx = __uint_as_float(lo_u);   // channel 2p
            float sy = __uint_as_float(hi_u);   // channel 2p+1
#pragma unroll
            for (int off = 16; off; off >>= 1) {
                sx += __shfl_xor_sync(0xFFFFFFFFu, sx, off);
                sy += __shfl_xor_sync(0xFFFFFFFFu, sy, off);
            }
            if (lane == (p * 4 + r)) {
                const int v = v0 + r;
                float2 res;
                res.x = alpha * sx;
                res.y = alpha * sy;
                if (beta != 0.0f) {
                    float2 pv = Pp[(size_t)p * V + v];
                    res.x += beta * pv.x;
                    res.y += beta * pv.y;
                }
                Op[(size_t)p * V + v] = res;
            }
        }
    }
}

// interleave x into g_xp
__global__ void prep_x(const float* __restrict__ x)
{
    const int v = blockIdx.x * blockDim.x + threadIdx.x;
    const int p = blockIdx.y;
    g_xp[(size_t)p * V + v] =
        make_float2(x[(size_t)(2 * p) * V + v], x[(size_t)(2 * p + 1) * V + v]);
}

// out[o][v] = bias[o] + sum_k sum_p (Tk[p][v].x * W[k][2p][o] + .y * W[k][2p+1][o])
__global__ __launch_bounds__(128)
void cheb_combine(const float* __restrict__ Wt,
                  const float* __restrict__ bias,
                  float* __restrict__ out)
{
    __shared__ float Ws[KORD * CIN * COUT];
    __shared__ float bs[COUT];
    const int tid = threadIdx.x;
    for (int idx = tid; idx < KORD * CIN * COUT; idx += blockDim.x) Ws[idx] = Wt[idx];
    if (tid < COUT) bs[tid] = bias[tid];
    __syncthreads();

    const int v = blockIdx.x * blockDim.x + tid;

    float acc[COUT];
#pragma unroll
    for (int o = 0; o < COUT; o++) acc[o] = bs[o];

#pragma unroll
    for (int k = 0; k < KORD; k++) {
        const float2* T = (k == 0) ? g_xp : g_Tp[k - 1];
#pragma unroll
        for (int p = 0; p < NP; p++) {
            float2 tv = T[(size_t)p * V + v];
            const float* w0 = &Ws[(k * CIN + 2 * p) * COUT];
            const float* w1 = w0 + COUT;
#pragma unroll
            for (int o = 0; o < COUT; o++)
                acc[o] = fmaf(tv.x, w0[o], fmaf(tv.y, w1[o], acc[o]));
        }
    }
#pragma unroll
    for (int o = 0; o < COUT; o++) out[(size_t)o * V + v] = acc[o];
}

extern "C" void kernel_launch(void* const* d_in, const int* in_sizes, int n_in,
                              void* d_out, int out_size)
{
    const float* x  = (const float*)d_in[0];
    const float* L  = (const float*)d_in[1];
    const float* Wt = (const float*)d_in[2];
    const float* b  = (const float*)d_in[3];
    float* out = (float*)d_out;

    float2* xp = nullptr;
    float2* Tp = nullptr;
    cudaGetSymbolAddress((void**)&xp, g_xp);
    cudaGetSymbolAddress((void**)&Tp, g_Tp);

    prep_x<<<dim3(V / 256, NP), 256>>>(x);

    const dim3 grid(V / VT);   // 384 CTAs
    const dim3 blk(256);

    // T1 = x @ L^T
    cheb_pass<<<grid, blk>>>(xp, L, xp, Tp + 0 * PV, 1.0f, 0.0f);
    // T2 = 2 T1 @ L^T - x
    cheb_pass<<<grid, blk>>>(Tp + 0 * PV, L, xp, Tp + 1 * PV, 2.0f, -1.0f);
    // T3 = 2 T2 @ L^T - T1
    cheb_pass<<<grid, blk>>>(Tp + 1 * PV, L, Tp + 0 * PV, Tp + 2 * PV, 2.0f, -1.0f);
    // T4 = 2 T3 @ L^T - T2
    cheb_pass<<<grid, blk>>>(Tp + 2 * PV, L, Tp + 1 * PV, Tp + 3 * PV, 2.0f, -1.0f);
    // out = einsum + bias
    cheb_combine<<<V / 128, 128>>>(Wt, b, out);
}